// round 4
// baseline (speedup 1.0000x reference)
#include <cuda_runtime.h>
#include <math.h>

#define Bsz   4
#define Lsz   4096
#define Esz   1024
#define Hsz   16
#define Dsz   64
#define HEADS 64
#define SPLIT 16
#define CHUNK 256            // Lsz / SPLIT
#define GT    16             // tokens staged per group (phase 1)

#define PART   8320          // A(4096) + B(4096) + ks(64) + kc(64)
#define OFF_A  0
#define OFF_B  4096
#define OFF_KS 8192
#define OFF_KC 8256

typedef unsigned long long u64;

// Scratch (no allocations allowed in kernel_launch)
__device__ float g_part[HEADS * SPLIT * PART];   // ~34 MB
__device__ float g_kv[HEADS * PART];             // ~2.1 MB

// ---- packed f32x2 helpers (sm_103a FFMA2 path) -----------------------------
__device__ __forceinline__ void ffma2(u64& d, u64 a, u64 b) {
    asm("fma.rn.f32x2 %0, %1, %2, %0;" : "+l"(d) : "l"(a), "l"(b));
}
__device__ __forceinline__ u64 dup2(float x) {
    u64 r;
    asm("mov.b64 %0, {%1, %1};" : "=l"(r) : "f"(x));
    return r;
}
__device__ __forceinline__ float2 unpk(u64 v) {
    float2 r;
    asm("mov.b64 {%0, %1}, %2;" : "=f"(r.x), "=f"(r.y) : "l"(v));
    return r;
}

// ---------------------------------------------------------------------------
// Phase 1: per (head, L-split) partial accumulation.
//   threads 0..63  : A[d][m] += s_l*relu(k)[d] * (mask^2 folded) * v[m]
//   threads 64..127: B[d][m] with cos
// 8x8 thread tile, accumulators packed as f32x2 pairs along m.
// ---------------------------------------------------------------------------
__global__ __launch_bounds__(128) void k_phase1(const float* __restrict__ K,
                                                const float* __restrict__ V,
                                                const float* __restrict__ M) {
    int blk = blockIdx.x;
    int n  = blk >> 4;         // head (0..63)
    int sp = blk & 15;         // L split
    int b = n >> 4, h = n & 15;
    int l0 = sp * CHUNK;

    const float* kb = K + ((size_t)b * Lsz + l0) * Esz + h * Dsz;
    const float* vb = V + ((size_t)b * Lsz + l0) * Esz + h * Dsz;
    const float* mb = M + (size_t)b * Lsz + l0;

    __shared__ float ssh[CHUNK], csh[CHUNK], msh[CHUNK];
    __shared__ float skh[GT * 64];   // s_l * mask * relu(k)
    __shared__ float ckh[GT * 64];   // c_l * mask * relu(k)
    __shared__ float vmh[GT * 64];   // mask * v

    int t = threadIdx.x;

    // per-token sin/cos (mask folded) for the whole chunk
    for (int i = t; i < CHUNK; i += 128) {
        int l = l0 + i;
        float ang = 1.5707963267948966f * (float)(l + 1) / (float)Lsz;
        float m = mb[i];
        ssh[i] = sinf(ang) * m;
        csh[i] = cosf(ang) * m;
        msh[i] = m;
    }

    bool isA = (t < 64);
    int tt = t & 63;
    int dg = tt >> 3;          // d block: d = dg*8 .. dg*8+7
    int mg = tt & 7;           // m block: m = mg*8 .. mg*8+7
    const float* xsh = isA ? skh : ckh;

    u64 acc[8][4];             // 8 d-rows x 4 packed m-pairs
    #pragma unroll
    for (int i = 0; i < 8; ++i)
        #pragma unroll
        for (int j = 0; j < 4; ++j) acc[i][j] = 0ull;
    float aks = 0.f;           // ks[tt] for A-threads, kc[tt] for B-threads

    for (int g = 0; g < CHUNK / GT; ++g) {
        __syncthreads();
        // stage GT=16 tokens x 64 dims: 256 float4 across 128 threads
        #pragma unroll
        for (int j = 0; j < 2; ++j) {
            int e4 = j * 128 + t;
            int tok = e4 >> 4;
            int dd = (e4 & 15) * 4;
            int li = g * GT + tok;
            float4 k4 = *(const float4*)&kb[(size_t)li * Esz + dd];
            float4 v4 = *(const float4*)&vb[(size_t)li * Esz + dd];
            float s = ssh[li], c = csh[li], m = msh[li];
            float rx = fmaxf(k4.x, 0.f), ry = fmaxf(k4.y, 0.f);
            float rz = fmaxf(k4.z, 0.f), rw = fmaxf(k4.w, 0.f);
            *(float4*)&skh[tok * 64 + dd] = make_float4(rx * s, ry * s, rz * s, rw * s);
            *(float4*)&ckh[tok * 64 + dd] = make_float4(rx * c, ry * c, rz * c, rw * c);
            *(float4*)&vmh[tok * 64 + dd] = make_float4(v4.x * m, v4.y * m, v4.z * m, v4.w * m);
        }
        __syncthreads();

        // ks/kc column sums (each thread owns one d = tt)
        #pragma unroll
        for (int k = 0; k < GT; ++k) aks += xsh[k * 64 + tt];

        // 8x8 outer product, packed along m: 32 FFMA2 per token
        #pragma unroll
        for (int k = 0; k < GT; ++k) {
            float4 x0 = *(const float4*)&xsh[k * 64 + dg * 8];
            float4 x1 = *(const float4*)&xsh[k * 64 + dg * 8 + 4];
            ulonglong2 y01 = *(const ulonglong2*)&vmh[k * 64 + mg * 8];
            ulonglong2 y23 = *(const ulonglong2*)&vmh[k * 64 + mg * 8 + 4];
            float x[8] = { x0.x, x0.y, x0.z, x0.w, x1.x, x1.y, x1.z, x1.w };
            #pragma unroll
            for (int i = 0; i < 8; ++i) {
                u64 xx = dup2(x[i]);
                ffma2(acc[i][0], xx, y01.x);
                ffma2(acc[i][1], xx, y01.y);
                ffma2(acc[i][2], xx, y23.x);
                ffma2(acc[i][3], xx, y23.y);
            }
        }
    }

    float* p = g_part + (size_t)blk * PART;
    int off = isA ? OFF_A : OFF_B;
    #pragma unroll
    for (int i = 0; i < 8; ++i) {
        int d = dg * 8 + i;
        // packed pairs have identical memory layout to 4 consecutive floats
        *(ulonglong2*)&p[off + d * 64 + mg * 8]     = make_ulonglong2(acc[i][0], acc[i][1]);
        *(ulonglong2*)&p[off + d * 64 + mg * 8 + 4] = make_ulonglong2(acc[i][2], acc[i][3]);
    }
    p[(isA ? OFF_KS : OFF_KC) + tt] = aks;
}

// ---------------------------------------------------------------------------
// Reduce the SPLIT partials per head (deterministic, fixed order)
// 512 blocks: 8 slices of 1040 elements per head.
// ---------------------------------------------------------------------------
__global__ __launch_bounds__(256) void k_reduce() {
    int blk = blockIdx.x;
    int n = blk >> 3;
    int sl = blk & 7;
    int base = sl * 1040;
    for (int i = base + threadIdx.x; i < base + 1040; i += 256) {
        float s = 0.f;
        #pragma unroll
        for (int sp = 0; sp < SPLIT; ++sp)
            s += g_part[(size_t)(n * SPLIT + sp) * PART + i];
        g_kv[(size_t)n * PART + i] = s;
    }
}

// ---------------------------------------------------------------------------
// Phase 2: out[l][m] = z_l * ( rqs[l]@A + rqc[l]@B )[m]
//   rqs = s_l*relu(q), rqc = c_l*relu(q) folded at staging time.
// Tile: 128 tokens x 64 m, thread tile 8 tok x 8 m, f32x2 packed along m.
// ---------------------------------------------------------------------------
#define TT    128
#define RQS   65
#define SM2_FLOATS (4096 + 4096 + 2 * TT * RQS + 3 * TT + 128)
#define SM2_BYTES  (SM2_FLOATS * 4)

__global__ __launch_bounds__(128) void k_phase2(const float* __restrict__ Q,
                                                float* __restrict__ O) {
    extern __shared__ float sm2[];
    float* Ash  = sm2;
    float* Bsh  = sm2 + 4096;
    float* rqs  = sm2 + 8192;
    float* rqc  = rqs + TT * RQS;
    float* ssh  = rqc + TT * RQS;
    float* csh  = ssh + TT;
    float* zsh  = csh + TT;
    float* ks2  = zsh + TT;
    float* kc2  = ks2 + 64;

    int blk = blockIdx.x;
    int n = blk >> 5;          // head
    int tile = blk & 31;       // 128-token tile
    int b = n >> 4, h = n & 15;
    int l0 = tile * TT;

    const float* qb = Q + ((size_t)b * Lsz + l0) * Esz + h * Dsz;
    const float* kv = g_kv + (size_t)n * PART;
    int t = threadIdx.x;

    #pragma unroll
    for (int j = 0; j < 8; ++j) {
        int e4 = j * 128 + t;
        *(float4*)&Ash[e4 * 4] = *(const float4*)&kv[OFF_A + e4 * 4];
        *(float4*)&Bsh[e4 * 4] = *(const float4*)&kv[OFF_B + e4 * 4];
    }
    if (t < 64) {
        ks2[t] = kv[OFF_KS + t];
        kc2[t] = kv[OFF_KC + t];
    }
    {
        int l = l0 + t;
        float ang = 1.5707963267948966f * (float)(l + 1) / (float)Lsz;
        ssh[t] = sinf(ang);
        csh[t] = cosf(ang);
    }
    __syncthreads();

    // stage s*relu(q), c*relu(q): [tok][d], row stride 65
    #pragma unroll
    for (int j = 0; j < 16; ++j) {
        int e4 = j * 128 + t;
        int tok = e4 >> 4;
        int dd = (e4 & 15) * 4;
        float s = ssh[tok], c = csh[tok];
        float4 q4 = *(const float4*)&qb[(size_t)tok * Esz + dd];
        float rx = fmaxf(q4.x, 0.f), ry = fmaxf(q4.y, 0.f);
        float rz = fmaxf(q4.z, 0.f), rw = fmaxf(q4.w, 0.f);
        float* rs = &rqs[tok * RQS + dd];
        float* rc = &rqc[tok * RQS + dd];
        rs[0] = rx * s; rs[1] = ry * s; rs[2] = rz * s; rs[3] = rw * s;
        rc[0] = rx * c; rc[1] = ry * c; rc[2] = rz * c; rc[3] = rw * c;
    }
    __syncthreads();

    // normalizer: one token per thread
    {
        float a = 0.f;
        const float* rs = &rqs[t * RQS];
        const float* rc = &rqc[t * RQS];
        #pragma unroll 8
        for (int d = 0; d < 64; ++d)
            a += rs[d] * ks2[d] + rc[d] * kc2[d];
        zsh[t] = 1.f / fmaxf(a, 1e-6f);
    }
    __syncthreads();

    int tg = t >> 3;           // token group (0..15)
    int mg = t & 7;            // m group
    int m0 = mg * 8;

    u64 acc[8][4];
    #pragma unroll
    for (int i = 0; i < 8; ++i)
        #pragma unroll
        for (int j = 0; j < 4; ++j) acc[i][j] = 0ull;

    #pragma unroll 4
    for (int d = 0; d < 64; ++d) {
        float ra[8], rb[8];
        #pragma unroll
        for (int i = 0; i < 8; ++i) {
            ra[i] = rqs[(tg * 8 + i) * RQS + d];
            rb[i] = rqc[(tg * 8 + i) * RQS + d];
        }
        ulonglong2 A01 = *(const ulonglong2*)&Ash[d * 64 + m0];
        ulonglong2 A23 = *(const ulonglong2*)&Ash[d * 64 + m0 + 4];
        ulonglong2 B01 = *(const ulonglong2*)&Bsh[d * 64 + m0];
        ulonglong2 B23 = *(const ulonglong2*)&Bsh[d * 64 + m0 + 4];
        #pragma unroll
        for (int i = 0; i < 8; ++i) {
            u64 ua = dup2(ra[i]);
            u64 ub = dup2(rb[i]);
            ffma2(acc[i][0], ua, A01.x);
            ffma2(acc[i][1], ua, A01.y);
            ffma2(acc[i][2], ua, A23.x);
            ffma2(acc[i][3], ua, A23.y);
            ffma2(acc[i][0], ub, B01.x);
            ffma2(acc[i][1], ub, B01.y);
            ffma2(acc[i][2], ub, B23.x);
            ffma2(acc[i][3], ub, B23.y);
        }
    }

    float* ob = O + ((size_t)n * Lsz + l0) * Dsz;
    #pragma unroll
    for (int i = 0; i < 8; ++i) {
        int tok = tg * 8 + i;
        float z = zsh[tok];
        float2 p0 = unpk(acc[i][0]), p1 = unpk(acc[i][1]);
        float2 p2 = unpk(acc[i][2]), p3 = unpk(acc[i][3]);
        *(float4*)&ob[(size_t)tok * Dsz + m0] =
            make_float4(p0.x * z, p0.y * z, p1.x * z, p1.y * z);
        *(float4*)&ob[(size_t)tok * Dsz + m0 + 4] =
            make_float4(p2.x * z, p2.y * z, p3.x * z, p3.y * z);
    }
}

// ---------------------------------------------------------------------------
extern "C" void kernel_launch(void* const* d_in, const int* in_sizes, int n_in,
                              void* d_out, int out_size) {
    const float* q = (const float*)d_in[0];
    const float* k = (const float*)d_in[1];
    const float* v = (const float*)d_in[2];
    const float* m = (const float*)d_in[3];
    float* out = (float*)d_out;

    cudaFuncSetAttribute(k_phase2, cudaFuncAttributeMaxDynamicSharedMemorySize,
                         SM2_BYTES);

    k_phase1<<<HEADS * SPLIT, 128>>>(k, v, m);
    k_reduce<<<HEADS * 8, 256>>>();
    k_phase2<<<HEADS * 32, 128, SM2_BYTES>>>(q, out);
}

// round 5
// speedup vs baseline: 1.6824x; 1.6824x over previous
#include <cuda_runtime.h>
#include <cuda_bf16.h>
#include <math.h>

#define Bsz   4
#define Lsz   4096
#define Esz   1024
#define HEADS 64
#define SPLIT 16
#define CHUNK 256            // tokens per phase-1 block
#define KC    32             // tokens staged per chunk (2 k-steps of 16)

#define PART   8320          // X-matrix 128x64 (8192) + w vector (128)
#define OFF_W  8192

typedef unsigned int u32;

// Scratch (no allocations allowed anywhere)
__device__ float g_part[HEADS * SPLIT * PART];            // ~34 MB fp32 partials
__device__ __nv_bfloat16 g_kvt_h[HEADS * 8192];           // KV^T hi  [head][m][f]
__device__ __nv_bfloat16 g_kvt_l[HEADS * 8192];           // KV^T lo
__device__ float g_w[HEADS * 128];                        // [ks||kc] fp32

// ---- helpers ---------------------------------------------------------------
__device__ __forceinline__ void mma_bf16(float* c, const u32* a, u32 b0, u32 b1) {
    asm("mma.sync.aligned.m16n8k16.row.col.f32.bf16.bf16.f32 "
        "{%0,%1,%2,%3}, {%4,%5,%6,%7}, {%8,%9}, {%0,%1,%2,%3};"
        : "+f"(c[0]), "+f"(c[1]), "+f"(c[2]), "+f"(c[3])
        : "r"(a[0]), "r"(a[1]), "r"(a[2]), "r"(a[3]), "r"(b0), "r"(b1));
}
__device__ __forceinline__ void bsplit(float x, __nv_bfloat16* ph, __nv_bfloat16* pl) {
    __nv_bfloat16 h = __float2bfloat16(x);
    *ph = h;
    *pl = __float2bfloat16(x - __bfloat162float(h));
}
__device__ __forceinline__ u32 ld32(const __nv_bfloat16* p) {
    return *(const u32*)p;
}
__device__ __forceinline__ u32 pack2(__nv_bfloat16 a, __nv_bfloat16 b) {
    u32 lo = *(unsigned short*)&a, hi = *(unsigned short*)&b;
    return lo | (hi << 16);
}

// ---------------------------------------------------------------------------
// Phase 1: per (head, 256-token split) compute partial
//   D[f][m] = sum_l X[f][l] * Y[l][m],  f in [0,128)
//   X rows 0..63 = s_l*mask*relu(k)[d], rows 64..127 = c_l*mask*relu(k)[d]
//   Y = mask*v.   Tensor-core bf16 split (hh+hl+lh), fp32 accum.
//   w[f] = sum_l X[f][l] accumulated in exact fp32 on the side.
// ---------------------------------------------------------------------------
#define XS 36     // smem row stride (bf16 elems)

__global__ __launch_bounds__(128) void k_phase1(const float* __restrict__ K,
                                                const float* __restrict__ V,
                                                const float* __restrict__ M) {
    int blk = blockIdx.x;
    int n  = blk >> 4;         // head
    int sp = blk & 15;
    int b = n >> 4, h = n & 15;
    int l0 = sp * CHUNK;

    const float* kb = K + ((size_t)b * Lsz + l0) * Esz + h * 64;
    const float* vb = V + ((size_t)b * Lsz + l0) * Esz + h * 64;
    const float* mb = M + (size_t)b * Lsz + l0;

    __shared__ __nv_bfloat16 Xh[128 * XS], Xl[128 * XS];
    __shared__ __nv_bfloat16 Th[64 * XS],  Tl[64 * XS];    // Y^T = (mask*v)^T
    __shared__ float ssh[CHUNK], csh[CHUNK], msh[CHUNK];
    __shared__ float ksp[8 * 128];

    int t = threadIdx.x;
    for (int i = t; i < CHUNK; i += 128) {
        int l = l0 + i;
        float ang = 1.5707963267948966f * (float)(l + 1) / (float)Lsz;
        float m = mb[i];
        ssh[i] = sinf(ang) * m;
        csh[i] = cosf(ang) * m;
        msh[i] = m;
    }

    int w  = t >> 5, lane = t & 31;
    int gid = lane >> 2, tid = lane & 3;
    int r0 = w * 32;
    int ddg = (t & 15) * 4;     // fixed feature group for staging/ks
    int rr  = t >> 4;           // fixed token-phase (0..7) for ks partials

    float acc[2][8][4];
    #pragma unroll
    for (int i = 0; i < 2; ++i)
        #pragma unroll
        for (int j = 0; j < 8; ++j)
            #pragma unroll
            for (int q = 0; q < 4; ++q) acc[i][j][q] = 0.f;
    float ksr[4] = {0,0,0,0}, kcr[4] = {0,0,0,0};

    for (int g = 0; g < CHUNK / KC; ++g) {
        __syncthreads();
        // stage KC=32 tokens x 64 dims, transposed + bf16-split
        #pragma unroll
        for (int j = 0; j < 4; ++j) {
            int tok = j * 8 + rr;                 // 0..31
            int li = g * KC + tok;
            float4 k4 = *(const float4*)&kb[(size_t)li * Esz + ddg];
            float4 v4 = *(const float4*)&vb[(size_t)li * Esz + ddg];
            float s = ssh[li], c = csh[li], m = msh[li];
            float kk[4] = { k4.x, k4.y, k4.z, k4.w };
            float vv[4] = { v4.x, v4.y, v4.z, v4.w };
            #pragma unroll
            for (int i = 0; i < 4; ++i) {
                float rk = fmaxf(kk[i], 0.f);
                float sk = rk * s, ck = rk * c, vm = vv[i] * m;
                ksr[i] += sk; kcr[i] += ck;
                int f = ddg + i;
                bsplit(sk, &Xh[f * XS + tok],        &Xl[f * XS + tok]);
                bsplit(ck, &Xh[(64 + f) * XS + tok], &Xl[(64 + f) * XS + tok]);
                bsplit(vm, &Th[f * XS + tok],        &Tl[f * XS + tok]);
            }
        }
        __syncthreads();

        #pragma unroll
        for (int ko = 0; ko < KC; ko += 16) {
            u32 ah[2][4], al[2][4];
            #pragma unroll
            for (int i = 0; i < 2; ++i) {
                int rb = r0 + 16 * i;
                ah[i][0] = ld32(&Xh[(rb + gid) * XS + ko + tid * 2]);
                ah[i][1] = ld32(&Xh[(rb + gid + 8) * XS + ko + tid * 2]);
                ah[i][2] = ld32(&Xh[(rb + gid) * XS + ko + 8 + tid * 2]);
                ah[i][3] = ld32(&Xh[(rb + gid + 8) * XS + ko + 8 + tid * 2]);
                al[i][0] = ld32(&Xl[(rb + gid) * XS + ko + tid * 2]);
                al[i][1] = ld32(&Xl[(rb + gid + 8) * XS + ko + tid * 2]);
                al[i][2] = ld32(&Xl[(rb + gid) * XS + ko + 8 + tid * 2]);
                al[i][3] = ld32(&Xl[(rb + gid + 8) * XS + ko + 8 + tid * 2]);
            }
            #pragma unroll
            for (int j = 0; j < 8; ++j) {
                int nb = j * 8;
                u32 bh0 = ld32(&Th[(nb + gid) * XS + ko + tid * 2]);
                u32 bh1 = ld32(&Th[(nb + gid) * XS + ko + 8 + tid * 2]);
                u32 bl0 = ld32(&Tl[(nb + gid) * XS + ko + tid * 2]);
                u32 bl1 = ld32(&Tl[(nb + gid) * XS + ko + 8 + tid * 2]);
                #pragma unroll
                for (int i = 0; i < 2; ++i) {
                    mma_bf16(acc[i][j], ah[i], bh0, bh1);
                    mma_bf16(acc[i][j], ah[i], bl0, bl1);
                    mma_bf16(acc[i][j], al[i], bh0, bh1);
                }
            }
        }
    }

    float* p = g_part + (size_t)blk * PART;
    #pragma unroll
    for (int i = 0; i < 2; ++i) {
        int r = r0 + 16 * i + gid;
        #pragma unroll
        for (int j = 0; j < 8; ++j) {
            int nb = j * 8 + tid * 2;
            *(float2*)&p[r * 64 + nb]       = make_float2(acc[i][j][0], acc[i][j][1]);
            *(float2*)&p[(r + 8) * 64 + nb] = make_float2(acc[i][j][2], acc[i][j][3]);
        }
    }
    #pragma unroll
    for (int i = 0; i < 4; ++i) {
        ksp[rr * 128 + ddg + i]      = ksr[i];
        ksp[rr * 128 + 64 + ddg + i] = kcr[i];
    }
    __syncthreads();
    {
        float s = 0.f;
        #pragma unroll
        for (int r = 0; r < 8; ++r) s += ksp[r * 128 + t];
        p[OFF_W + t] = s;
    }
}

// ---------------------------------------------------------------------------
// Reduce: sum SPLIT fp32 partials; emit KV^T as bf16 hi/lo planes + fp32 w.
// ---------------------------------------------------------------------------
__global__ __launch_bounds__(256) void k_reduce() {
    int blk = blockIdx.x;
    int n = blk >> 2;          // head
    int sl = blk & 3;
    int t = threadIdx.x;
    for (int idx = sl * 2048 + t; idx < sl * 2048 + 2048; idx += 256) {
        int f = idx >> 6, m = idx & 63;
        float s = 0.f;
        #pragma unroll
        for (int sp = 0; sp < SPLIT; ++sp)
            s += g_part[(size_t)(n * SPLIT + sp) * PART + idx];
        __nv_bfloat16 hh, ll;
        bsplit(s, &hh, &ll);
        g_kvt_h[(size_t)n * 8192 + m * 128 + f] = hh;
        g_kvt_l[(size_t)n * 8192 + m * 128 + f] = ll;
    }
    if (sl == 0 && t < 128) {
        float s = 0.f;
        #pragma unroll
        for (int sp = 0; sp < SPLIT; ++sp)
            s += g_part[(size_t)(n * SPLIT + sp) * PART + OFF_W + t];
        g_w[n * 128 + t] = s;
    }
}

// ---------------------------------------------------------------------------
// Phase 2: out[l][m] = z_l * (Rq[l] @ KV)[m],  Rq = [s*relu(q) | c*relu(q)]
// 64-token x 64-m tile, K=128, bf16 split MMA; z in exact fp32.
// ---------------------------------------------------------------------------
#define FS 132
#define X2H_OFF  0
#define X2L_OFF  (64 * FS * 2)
#define KH_OFF   (2 * 64 * FS * 2)
#define KL_OFF   (3 * 64 * FS * 2)
#define FP_OFF   (4 * 64 * FS * 2)
// floats after FP_OFF: wsh[128] | zp[1024] | zsh[64] | ssh[64] | csh[64]
#define SM2_BYTES (FP_OFF + (128 + 1024 + 64 * 3) * 4)

__global__ __launch_bounds__(128) void k_phase2(const float* __restrict__ Q,
                                                float* __restrict__ O) {
    extern __shared__ char sm2[];
    __nv_bfloat16* X2h = (__nv_bfloat16*)(sm2 + X2H_OFF);
    __nv_bfloat16* X2l = (__nv_bfloat16*)(sm2 + X2L_OFF);
    __nv_bfloat16* Kh  = (__nv_bfloat16*)(sm2 + KH_OFF);
    __nv_bfloat16* Kl  = (__nv_bfloat16*)(sm2 + KL_OFF);
    float* wsh = (float*)(sm2 + FP_OFF);
    float* zp  = wsh + 128;
    float* zsh = zp + 1024;
    float* ssh = zsh + 64;
    float* csh = ssh + 64;

    int blk = blockIdx.x;
    int n = blk >> 6;          // head
    int tile = blk & 63;
    int b = n >> 4, h = n & 15;
    int l0 = tile * 64;

    const float* qb = Q + ((size_t)b * Lsz + l0) * Esz + h * 64;
    int t = threadIdx.x;

    if (t < 128) wsh[t] = g_w[n * 128 + t];
    if (t < 64) {
        int l = l0 + t;
        float ang = 1.5707963267948966f * (float)(l + 1) / (float)Lsz;
        ssh[t] = sinf(ang);
        csh[t] = cosf(ang);
    }
    // copy KV^T hi/lo (rows of 128, padded stride FS), 8B chunks
    for (int idx = t; idx < 2048; idx += 128) {
        int m = idx >> 5, c = idx & 31;
        *(uint2*)&Kh[m * FS + c * 4] =
            *(const uint2*)&g_kvt_h[(size_t)n * 8192 + m * 128 + c * 4];
        *(uint2*)&Kl[m * FS + c * 4] =
            *(const uint2*)&g_kvt_l[(size_t)n * 8192 + m * 128 + c * 4];
    }
    __syncthreads();   // ssh/csh/wsh ready before staging uses them

    // stage Rq (bf16 split) + z partials (exact fp32)
    int ddg = (t & 15) * 4;
    #pragma unroll
    for (int j = 0; j < 8; ++j) {
        int e4 = j * 128 + t;
        int tok = e4 >> 4;                  // 0..63
        float s = ssh[tok], c = csh[tok];
        float4 q4 = *(const float4*)&qb[(size_t)tok * Esz + ddg];
        float rq[4] = { fmaxf(q4.x, 0.f), fmaxf(q4.y, 0.f),
                        fmaxf(q4.z, 0.f), fmaxf(q4.w, 0.f) };
        float zpart = 0.f;
        __nv_bfloat16 hs[4], ls[4], hc[4], lc[4];
        #pragma unroll
        for (int i = 0; i < 4; ++i) {
            float xs = rq[i] * s, xc = rq[i] * c;
            zpart += xs * wsh[ddg + i] + xc * wsh[64 + ddg + i];
            bsplit(xs, &hs[i], &ls[i]);
            bsplit(xc, &hc[i], &lc[i]);
        }
        *(u32*)&X2h[tok * FS + ddg]          = pack2(hs[0], hs[1]);
        *(u32*)&X2h[tok * FS + ddg + 2]      = pack2(hs[2], hs[3]);
        *(u32*)&X2l[tok * FS + ddg]          = pack2(ls[0], ls[1]);
        *(u32*)&X2l[tok * FS + ddg + 2]      = pack2(ls[2], ls[3]);
        *(u32*)&X2h[tok * FS + 64 + ddg]     = pack2(hc[0], hc[1]);
        *(u32*)&X2h[tok * FS + 64 + ddg + 2] = pack2(hc[2], hc[3]);
        *(u32*)&X2l[tok * FS + 64 + ddg]     = pack2(lc[0], lc[1]);
        *(u32*)&X2l[tok * FS + 64 + ddg + 2] = pack2(lc[2], lc[3]);
        zp[tok * 16 + (t & 15)] = zpart;
    }
    __syncthreads();
    if (t < 64) {
        float a = 0.f;
        #pragma unroll
        for (int g = 0; g < 16; ++g) a += zp[t * 16 + g];
        zsh[t] = 1.f / fmaxf(a, 1e-6f);
    }
    __syncthreads();

    int w = t >> 5, lane = t & 31;
    int gid = lane >> 2, tid = lane & 3;
    int t0 = w * 16;

    float acc[8][4];
    #pragma unroll
    for (int j = 0; j < 8; ++j)
        #pragma unroll
        for (int q = 0; q < 4; ++q) acc[j][q] = 0.f;

    #pragma unroll
    for (int ko = 0; ko < 128; ko += 16) {
        u32 ah[4], al[4];
        ah[0] = ld32(&X2h[(t0 + gid) * FS + ko + tid * 2]);
        ah[1] = ld32(&X2h[(t0 + gid + 8) * FS + ko + tid * 2]);
        ah[2] = ld32(&X2h[(t0 + gid) * FS + ko + 8 + tid * 2]);
        ah[3] = ld32(&X2h[(t0 + gid + 8) * FS + ko + 8 + tid * 2]);
        al[0] = ld32(&X2l[(t0 + gid) * FS + ko + tid * 2]);
        al[1] = ld32(&X2l[(t0 + gid + 8) * FS + ko + tid * 2]);
        al[2] = ld32(&X2l[(t0 + gid) * FS + ko + 8 + tid * 2]);
        al[3] = ld32(&X2l[(t0 + gid + 8) * FS + ko + 8 + tid * 2]);
        #pragma unroll
        for (int j = 0; j < 8; ++j) {
            int nb = j * 8;
            u32 bh0 = ld32(&Kh[(nb + gid) * FS + ko + tid * 2]);
            u32 bh1 = ld32(&Kh[(nb + gid) * FS + ko + 8 + tid * 2]);
            u32 bl0 = ld32(&Kl[(nb + gid) * FS + ko + tid * 2]);
            u32 bl1 = ld32(&Kl[(nb + gid) * FS + ko + 8 + tid * 2]);
            mma_bf16(acc[j], ah, bh0, bh1);
            mma_bf16(acc[j], ah, bl0, bl1);
            mma_bf16(acc[j], al, bh0, bh1);
        }
    }

    float* ob = O + ((size_t)n * Lsz + l0) * 64;
    int r1 = t0 + gid;
    float z1 = zsh[r1], z2 = zsh[r1 + 8];
    #pragma unroll
    for (int j = 0; j < 8; ++j) {
        int nb = j * 8 + tid * 2;
        *(float2*)&ob[(size_t)r1 * 64 + nb] =
            make_float2(acc[j][0] * z1, acc[j][1] * z1);
        *(float2*)&ob[(size_t)(r1 + 8) * 64 + nb] =
            make_float2(acc[j][2] * z2, acc[j][3] * z2);
    }
}

// ---------------------------------------------------------------------------
extern "C" void kernel_launch(void* const* d_in, const int* in_sizes, int n_in,
                              void* d_out, int out_size) {
    const float* q = (const float*)d_in[0];
    const float* k = (const float*)d_in[1];
    const float* v = (const float*)d_in[2];
    const float* m = (const float*)d_in[3];
    float* out = (float*)d_out;

    cudaFuncSetAttribute(k_phase2, cudaFuncAttributeMaxDynamicSharedMemorySize,
                         SM2_BYTES);

    k_phase1<<<HEADS * SPLIT, 128>>>(k, v, m);
    k_reduce<<<HEADS * 4, 256>>>();
    k_phase2<<<HEADS * 64, 128, SM2_BYTES>>>(q, out);
}

// round 6
// speedup vs baseline: 1.7929x; 1.0657x over previous
#include <cuda_runtime.h>
#include <cuda_bf16.h>
#include <math.h>

#define Bsz   4
#define Lsz   4096
#define Esz   1024
#define HEADS 64
#define SPLIT 8
#define CHUNK 512            // tokens per phase-1 block
#define KC    32             // tokens staged per group (2 k-steps of 16)

#define PART   8320          // D-matrix 128x64 (8192) + w vector (128)
#define OFF_W  8192

typedef unsigned int u32;

// Scratch (no allocations allowed anywhere)
__device__ float g_part[HEADS * SPLIT * PART];            // ~17 MB fp32 partials
__device__ __nv_bfloat16 g_kvt_h[HEADS * 8192];           // KV^T hi  [head][m][f]
__device__ __nv_bfloat16 g_kvt_l[HEADS * 8192];           // KV^T lo
__device__ float g_w[HEADS * 128];                        // [ks||kc] fp32

// ---- helpers ---------------------------------------------------------------
__device__ __forceinline__ void mma_bf16(float* c, const u32* a, u32 b0, u32 b1) {
    asm("mma.sync.aligned.m16n8k16.row.col.f32.bf16.bf16.f32 "
        "{%0,%1,%2,%3}, {%4,%5,%6,%7}, {%8,%9}, {%0,%1,%2,%3};"
        : "+f"(c[0]), "+f"(c[1]), "+f"(c[2]), "+f"(c[3])
        : "r"(a[0]), "r"(a[1]), "r"(a[2]), "r"(a[3]), "r"(b0), "r"(b1));
}
__device__ __forceinline__ u32 sh_addr(const void* p) {
    return (u32)__cvta_generic_to_shared(p);
}
__device__ __forceinline__ void ldsm4(u32* r, u32 a) {
    asm volatile("ldmatrix.sync.aligned.m8n8.x4.shared.b16 {%0,%1,%2,%3}, [%4];"
        : "=r"(r[0]), "=r"(r[1]), "=r"(r[2]), "=r"(r[3]) : "r"(a));
}
__device__ __forceinline__ void ldsm4t(u32* r, u32 a) {
    asm volatile("ldmatrix.sync.aligned.m8n8.x4.trans.shared.b16 {%0,%1,%2,%3}, [%4];"
        : "=r"(r[0]), "=r"(r[1]), "=r"(r[2]), "=r"(r[3]) : "r"(a));
}
__device__ __forceinline__ void bsplit(float x, __nv_bfloat16* ph, __nv_bfloat16* pl) {
    __nv_bfloat16 h = __float2bfloat16(x);
    *ph = h;
    *pl = __float2bfloat16(x - __bfloat162float(h));
}
__device__ __forceinline__ u32 pack2(__nv_bfloat16 a, __nv_bfloat16 b) {
    u32 lo = *(unsigned short*)&a, hi = *(unsigned short*)&b;
    return lo | (hi << 16);
}

// ---------------------------------------------------------------------------
// Phase 1: per (head, 512-token split):
//   D[f][m] = sum_l X[f][l]*Y[l][m]; X = [s*mask*relu(k) ; c*mask*relu(k)],
//   Y = mask*v. bf16 split (hh+hl+lh) tensor MMA, fp32 accumulate.
//   w[f] = sum_l X[f][l] in exact fp32.
// Staging is token-major: X[tok][f], Y[tok][m] -> packed 8B stores,
// fragments via ldmatrix.trans.
// ---------------------------------------------------------------------------
#define XSTR 136
#define TSTR 72

__global__ __launch_bounds__(128) void k_phase1(const float* __restrict__ K,
                                                const float* __restrict__ V,
                                                const float* __restrict__ M) {
    int blk = blockIdx.x;
    int n  = blk >> 3;         // head
    int sp = blk & 7;
    int b = n >> 4, h = n & 15;
    int l0 = sp * CHUNK;

    const float* kb = K + ((size_t)b * Lsz + l0) * Esz + h * 64;
    const float* vb = V + ((size_t)b * Lsz + l0) * Esz + h * 64;
    const float* mb = M + (size_t)b * Lsz + l0;

    __shared__ __nv_bfloat16 Xh[KC * XSTR], Xl[KC * XSTR];
    __shared__ __nv_bfloat16 Th[KC * TSTR], Tl[KC * TSTR];
    __shared__ float ssh[CHUNK], csh[CHUNK], msh[CHUNK];
    __shared__ float ksp[8 * 128];

    int t = threadIdx.x;
    for (int i = t; i < CHUNK; i += 128) {
        int l = l0 + i;
        float ang = 1.5707963267948966f * (float)(l + 1) / (float)Lsz;
        float m = mb[i];
        ssh[i] = sinf(ang) * m;
        csh[i] = cosf(ang) * m;
        msh[i] = m;
    }

    int w = t >> 5, lane = t & 31;
    int gid = lane >> 2, tid = lane & 3;
    int rb = w * 32;
    int ddg = (t & 15) * 4;    // feature group for staging
    int pr  = t >> 4;          // token phase 0..7

    // ldmatrix.trans per-lane offsets: row (k/tok) and col
    int ra = (lane & 7) + ((lane >> 4) & 1) * 8;
    int ca = ((lane >> 3) & 1) * 8;

    float acc[2][8][4];
    #pragma unroll
    for (int i = 0; i < 2; ++i)
        #pragma unroll
        for (int j = 0; j < 8; ++j)
            #pragma unroll
            for (int q = 0; q < 4; ++q) acc[i][j][q] = 0.f;
    float ksr[4] = {0,0,0,0}, kcr[4] = {0,0,0,0};

    for (int g = 0; g < CHUNK / KC; ++g) {
        __syncthreads();
        // stage KC=32 tokens, token-major, packed 8B stores
        #pragma unroll
        for (int jj = 0; jj < 4; ++jj) {
            int tok = jj * 8 + pr;
            int li = g * KC + tok;
            float4 k4 = *(const float4*)&kb[(size_t)li * Esz + ddg];
            float4 v4 = *(const float4*)&vb[(size_t)li * Esz + ddg];
            float s = ssh[li], c = csh[li], m = msh[li];
            float kk[4] = { k4.x, k4.y, k4.z, k4.w };
            float vv[4] = { v4.x, v4.y, v4.z, v4.w };
            __nv_bfloat16 sh_[4], sl_[4], ch_[4], cl_[4], vh_[4], vl_[4];
            #pragma unroll
            for (int i = 0; i < 4; ++i) {
                float rk = fmaxf(kk[i], 0.f);
                float sk = rk * s, ck = rk * c, vm = vv[i] * m;
                ksr[i] += sk; kcr[i] += ck;
                bsplit(sk, &sh_[i], &sl_[i]);
                bsplit(ck, &ch_[i], &cl_[i]);
                bsplit(vm, &vh_[i], &vl_[i]);
            }
            *(uint2*)&Xh[tok * XSTR + ddg] =
                make_uint2(pack2(sh_[0], sh_[1]), pack2(sh_[2], sh_[3]));
            *(uint2*)&Xh[tok * XSTR + 64 + ddg] =
                make_uint2(pack2(ch_[0], ch_[1]), pack2(ch_[2], ch_[3]));
            *(uint2*)&Xl[tok * XSTR + ddg] =
                make_uint2(pack2(sl_[0], sl_[1]), pack2(sl_[2], sl_[3]));
            *(uint2*)&Xl[tok * XSTR + 64 + ddg] =
                make_uint2(pack2(cl_[0], cl_[1]), pack2(cl_[2], cl_[3]));
            *(uint2*)&Th[tok * TSTR + ddg] =
                make_uint2(pack2(vh_[0], vh_[1]), pack2(vh_[2], vh_[3]));
            *(uint2*)&Tl[tok * TSTR + ddg] =
                make_uint2(pack2(vl_[0], vl_[1]), pack2(vl_[2], vl_[3]));
        }
        __syncthreads();

        #pragma unroll
        for (int ko = 0; ko < KC; ko += 16) {
            u32 ah[2][4], al[2][4];
            #pragma unroll
            for (int i = 0; i < 2; ++i) {
                ldsm4t(ah[i], sh_addr(&Xh[(ko + ra) * XSTR + rb + i * 16 + ca]));
                ldsm4t(al[i], sh_addr(&Xl[(ko + ra) * XSTR + rb + i * 16 + ca]));
            }
            #pragma unroll
            for (int jp = 0; jp < 4; ++jp) {
                u32 bh[4], bl[4];
                ldsm4t(bh, sh_addr(&Th[(ko + ra) * TSTR + jp * 16 + ca]));
                ldsm4t(bl, sh_addr(&Tl[(ko + ra) * TSTR + jp * 16 + ca]));
                #pragma unroll
                for (int i = 0; i < 2; ++i) {
                    mma_bf16(acc[i][2 * jp],     ah[i], bh[0], bh[2]);
                    mma_bf16(acc[i][2 * jp],     ah[i], bl[0], bl[2]);
                    mma_bf16(acc[i][2 * jp],     al[i], bh[0], bh[2]);
                    mma_bf16(acc[i][2 * jp + 1], ah[i], bh[1], bh[3]);
                    mma_bf16(acc[i][2 * jp + 1], ah[i], bl[1], bl[3]);
                    mma_bf16(acc[i][2 * jp + 1], al[i], bh[1], bh[3]);
                }
            }
        }
    }

    float* p = g_part + (size_t)blk * PART;
    #pragma unroll
    for (int i = 0; i < 2; ++i) {
        int r = rb + 16 * i + gid;
        #pragma unroll
        for (int j = 0; j < 8; ++j) {
            int nb = j * 8 + tid * 2;
            *(float2*)&p[r * 64 + nb]       = make_float2(acc[i][j][0], acc[i][j][1]);
            *(float2*)&p[(r + 8) * 64 + nb] = make_float2(acc[i][j][2], acc[i][j][3]);
        }
    }
    #pragma unroll
    for (int i = 0; i < 4; ++i) {
        ksp[pr * 128 + ddg + i]      = ksr[i];
        ksp[pr * 128 + 64 + ddg + i] = kcr[i];
    }
    __syncthreads();
    {
        float s = 0.f;
        #pragma unroll
        for (int r = 0; r < 8; ++r) s += ksp[r * 128 + t];
        p[OFF_W + t] = s;
    }
}

// ---------------------------------------------------------------------------
// Reduce: sum SPLIT fp32 partials; emit KV^T bf16 hi/lo planes + fp32 w.
// ---------------------------------------------------------------------------
__global__ __launch_bounds__(256) void k_reduce() {
    int blk = blockIdx.x;
    int n = blk >> 2;
    int sl = blk & 3;
    int t = threadIdx.x;
    for (int idx = sl * 2048 + t; idx < sl * 2048 + 2048; idx += 256) {
        int f = idx >> 6, m = idx & 63;
        float s = 0.f;
        #pragma unroll
        for (int sp = 0; sp < SPLIT; ++sp)
            s += g_part[(size_t)(n * SPLIT + sp) * PART + idx];
        __nv_bfloat16 hh, ll;
        bsplit(s, &hh, &ll);
        g_kvt_h[(size_t)n * 8192 + m * 128 + f] = hh;
        g_kvt_l[(size_t)n * 8192 + m * 128 + f] = ll;
    }
    if (sl == 0 && t < 128) {
        float s = 0.f;
        #pragma unroll
        for (int sp = 0; sp < SPLIT; ++sp)
            s += g_part[(size_t)(n * SPLIT + sp) * PART + OFF_W + t];
        g_w[n * 128 + t] = s;
    }
}

// ---------------------------------------------------------------------------
// Phase 2: out[l][m] = z_l * (Rq[l] @ KV)[m]; Rq = [s*relu(q) | c*relu(q)]
// 64 tok x 64 m tile, K=128; ldmatrix (non-trans) both operands; z exact fp32.
// ---------------------------------------------------------------------------
#define FS2 136
#define X2H_OFF  0
#define X2L_OFF  (64 * FS2 * 2)
#define KH_OFF   (2 * 64 * FS2 * 2)
#define KL_OFF   (3 * 64 * FS2 * 2)
#define FP_OFF   (4 * 64 * FS2 * 2)
#define SM2_BYTES (FP_OFF + (128 + 1024 + 64 * 3) * 4)

__global__ __launch_bounds__(128) void k_phase2(const float* __restrict__ Q,
                                                float* __restrict__ O) {
    extern __shared__ char sm2[];
    __nv_bfloat16* X2h = (__nv_bfloat16*)(sm2 + X2H_OFF);
    __nv_bfloat16* X2l = (__nv_bfloat16*)(sm2 + X2L_OFF);
    __nv_bfloat16* Kh  = (__nv_bfloat16*)(sm2 + KH_OFF);
    __nv_bfloat16* Kl  = (__nv_bfloat16*)(sm2 + KL_OFF);
    float* wsh = (float*)(sm2 + FP_OFF);
    float* zp  = wsh + 128;
    float* zsh = zp + 1024;
    float* ssh = zsh + 64;
    float* csh = ssh + 64;

    int blk = blockIdx.x;
    int n = blk >> 6;
    int tile = blk & 63;
    int b = n >> 4, h = n & 15;
    int l0 = tile * 64;

    const float* qb = Q + ((size_t)b * Lsz + l0) * Esz + h * 64;
    int t = threadIdx.x;

    if (t < 128) wsh[t] = g_w[n * 128 + t];
    if (t < 64) {
        int l = l0 + t;
        float ang = 1.5707963267948966f * (float)(l + 1) / (float)Lsz;
        ssh[t] = sinf(ang);
        csh[t] = cosf(ang);
    }
    for (int idx = t; idx < 2048; idx += 128) {
        int mr = idx >> 5, c = idx & 31;
        *(uint2*)&Kh[mr * FS2 + c * 4] =
            *(const uint2*)&g_kvt_h[(size_t)n * 8192 + mr * 128 + c * 4];
        *(uint2*)&Kl[mr * FS2 + c * 4] =
            *(const uint2*)&g_kvt_l[(size_t)n * 8192 + mr * 128 + c * 4];
    }
    __syncthreads();

    int ddg = (t & 15) * 4;
    #pragma unroll
    for (int j = 0; j < 8; ++j) {
        int e4 = j * 128 + t;
        int tok = e4 >> 4;
        float s = ssh[tok], c = csh[tok];
        float4 q4 = *(const float4*)&qb[(size_t)tok * Esz + ddg];
        float rq[4] = { fmaxf(q4.x, 0.f), fmaxf(q4.y, 0.f),
                        fmaxf(q4.z, 0.f), fmaxf(q4.w, 0.f) };
        float zpart = 0.f;
        __nv_bfloat16 hs[4], ls[4], hc[4], lc[4];
        #pragma unroll
        for (int i = 0; i < 4; ++i) {
            float xs = rq[i] * s, xc = rq[i] * c;
            zpart += xs * wsh[ddg + i] + xc * wsh[64 + ddg + i];
            bsplit(xs, &hs[i], &ls[i]);
            bsplit(xc, &hc[i], &lc[i]);
        }
        *(uint2*)&X2h[tok * FS2 + ddg] =
            make_uint2(pack2(hs[0], hs[1]), pack2(hs[2], hs[3]));
        *(uint2*)&X2h[tok * FS2 + 64 + ddg] =
            make_uint2(pack2(hc[0], hc[1]), pack2(hc[2], hc[3]));
        *(uint2*)&X2l[tok * FS2 + ddg] =
            make_uint2(pack2(ls[0], ls[1]), pack2(ls[2], ls[3]));
        *(uint2*)&X2l[tok * FS2 + 64 + ddg] =
            make_uint2(pack2(lc[0], lc[1]), pack2(lc[2], lc[3]));
        zp[tok * 16 + (t & 15)] = zpart;
    }
    __syncthreads();
    if (t < 64) {
        float a = 0.f;
        #pragma unroll
        for (int g = 0; g < 16; ++g) a += zp[t * 16 + g];
        zsh[t] = 1.f / fmaxf(a, 1e-6f);
    }
    __syncthreads();

    int w = t >> 5, lane = t & 31;
    int gid = lane >> 2, tid = lane & 3;
    int t0 = w * 16;
    int rn = lane & 15;
    int cn = ((lane >> 4) & 1) * 8;

    float acc[8][4];
    #pragma unroll
    for (int j = 0; j < 8; ++j)
        #pragma unroll
        for (int q = 0; q < 4; ++q) acc[j][q] = 0.f;

    #pragma unroll
    for (int ko = 0; ko < 128; ko += 16) {
        u32 ah[4], al[4];
        ldsm4(ah, sh_addr(&X2h[(t0 + rn) * FS2 + ko + cn]));
        ldsm4(al, sh_addr(&X2l[(t0 + rn) * FS2 + ko + cn]));
        #pragma unroll
        for (int jp = 0; jp < 4; ++jp) {
            u32 bh[4], bl[4];
            ldsm4(bh, sh_addr(&Kh[(jp * 16 + rn) * FS2 + ko + cn]));
            ldsm4(bl, sh_addr(&Kl[(jp * 16 + rn) * FS2 + ko + cn]));
            mma_bf16(acc[2 * jp],     ah, bh[0], bh[2]);
            mma_bf16(acc[2 * jp],     ah, bl[0], bl[2]);
            mma_bf16(acc[2 * jp],     al, bh[0], bh[2]);
            mma_bf16(acc[2 * jp + 1], ah, bh[1], bh[3]);
            mma_bf16(acc[2 * jp + 1], ah, bl[1], bl[3]);
            mma_bf16(acc[2 * jp + 1], al, bh[1], bh[3]);
        }
    }

    float* ob = O + ((size_t)n * Lsz + l0) * 64;
    int r1 = t0 + gid;
    float z1 = zsh[r1], z2 = zsh[r1 + 8];
    #pragma unroll
    for (int j = 0; j < 8; ++j) {
        int nb = j * 8 + tid * 2;
        *(float2*)&ob[(size_t)r1 * 64 + nb] =
            make_float2(acc[j][0] * z1, acc[j][1] * z1);
        *(float2*)&ob[(size_t)(r1 + 8) * 64 + nb] =
            make_float2(acc[j][2] * z2, acc[j][3] * z2);
    }
}

// ---------------------------------------------------------------------------
extern "C" void kernel_launch(void* const* d_in, const int* in_sizes, int n_in,
                              void* d_out, int out_size) {
    const float* q = (const float*)d_in[0];
    const float* k = (const float*)d_in[1];
    const float* v = (const float*)d_in[2];
    const float* m = (const float*)d_in[3];
    float* out = (float*)d_out;

    cudaFuncSetAttribute(k_phase2, cudaFuncAttributeMaxDynamicSharedMemorySize,
                         SM2_BYTES);

    k_phase1<<<HEADS * SPLIT, 128>>>(k, v, m);
    k_reduce<<<HEADS * 4, 256>>>();
    k_phase2<<<HEADS * 64, 128, SM2_BYTES>>>(q, out);
}